// round 4
// baseline (speedup 1.0000x reference)
#include <cuda_runtime.h>
#include <cstdint>
#include <math.h>

// ============================================================================
// Quantizing_12060268167756 — VQ lookup via warp-level tf32 mma.sync + exact
// refine. (tcgen05 is unavailable: harness PTX target is sm_103 w/o 'a'.)
//   x: (16384, 512) f32   weight: (8192, 512) f32
//   out: q_data (N,E) f32, then q_idx (N,) as f32
// ============================================================================

#define E    512
#define NROW 16384
#define QROW 8192

#define BM   128
#define BN   128
#define BK   32
#define NQT  (QROW / BN)   // 64
#define NKC  (E / BK)      // 16
#define NIT  (NQT * NKC)   // 1024
#define STAGES 3
#define CAND_CAP 32

#define A_BYTES (BM * BK * 4)            // 16384
#define STAGE_BYTES (2 * A_BYTES)        // 32768

// dynamic smem offsets (bytes)
#define SOFF_STAGE 0
#define SOFF_WSQ   (STAGES * STAGE_BYTES)            // 98304, 32KB
#define SOFF_CAND  (SOFF_WSQ + QROW * 4)             // 131072, 64KB (256 thr x 32 x 8B)
#define SOFF_BEST  (SOFF_CAND + 256 * CAND_CAP * 8)  // 196608, 8KB (128 x 16 f32)
#define SOFF_CNT   (SOFF_BEST + BM * 16 * 4)         // 204800, 1KB
#define SMEM_TOTAL (SOFF_CNT + 256 * 4)              // 205824

__device__ float g_xsq[NROW];
__device__ float g_wsq[QROW];
__device__ int   g_idx[NROW];
__device__ unsigned int g_wsqmax_bits;

// ---------------------------------------------------------------------------
__device__ __forceinline__ uint32_t smem_u32(const void* p) {
    uint32_t a;
    asm("{ .reg .u64 t; cvta.to.shared.u64 t, %1; cvt.u32.u64 %0, t; }" : "=r"(a) : "l"(p));
    return a;
}
__device__ __forceinline__ void cp16(uint32_t dst, const void* src) {
    asm volatile("cp.async.cg.shared.global [%0], [%1], 16;"
                 :: "r"(dst), "l"(src) : "memory");
}
__device__ __forceinline__ void mma_tf32(float c[4], const uint32_t a[4], const uint32_t b[2]) {
    asm volatile(
        "mma.sync.aligned.m16n8k8.row.col.f32.tf32.tf32.f32 "
        "{%0,%1,%2,%3}, {%4,%5,%6,%7}, {%8,%9}, {%0,%1,%2,%3};"
        : "+f"(c[0]), "+f"(c[1]), "+f"(c[2]), "+f"(c[3])
        : "r"(a[0]), "r"(a[1]), "r"(a[2]), "r"(a[3]), "r"(b[0]), "r"(b[1]));
}

// ---------------------------------------------------------------------------
// Row sum-of-squares (fp64 accumulate -> correctly-rounded f32).
// ---------------------------------------------------------------------------
__global__ void __launch_bounds__(256) rowsq_x_kernel(const float* __restrict__ X)
{
    if (blockIdx.x == 0 && threadIdx.x == 0) g_wsqmax_bits = 0u;
    int row = blockIdx.x * 8 + (threadIdx.x >> 5);
    if (row >= NROW) return;
    int lane = threadIdx.x & 31;
    const float* p = X + (size_t)row * E;
    double s = 0.0;
    #pragma unroll
    for (int c = lane; c < E; c += 32) { float v = p[c]; s += (double)v * (double)v; }
    #pragma unroll
    for (int o = 16; o > 0; o >>= 1) s += __shfl_down_sync(0xffffffffu, s, o);
    if (lane == 0) g_xsq[row] = (float)s;
}

__global__ void __launch_bounds__(256) rowsq_w_kernel(const float* __restrict__ W)
{
    int row = blockIdx.x * 8 + (threadIdx.x >> 5);
    if (row >= QROW) return;
    int lane = threadIdx.x & 31;
    const float* p = W + (size_t)row * E;
    double s = 0.0;
    #pragma unroll
    for (int c = lane; c < E; c += 32) { float v = p[c]; s += (double)v * (double)v; }
    #pragma unroll
    for (int o = 16; o > 0; o >>= 1) s += __shfl_down_sync(0xffffffffu, s, o);
    if (lane == 0) {
        float f = (float)s;
        g_wsq[row] = f;
        atomicMax(&g_wsqmax_bits, (unsigned int)__float_as_int(f));  // f >= 0
    }
}

// ---------------------------------------------------------------------------
// Exact distance — bit-identical to R1's (which matched the reference).
// Serial ascending-k fp32 FMA chain; t = fl(xs - 2*acc); d = t + wsq.
// ---------------------------------------------------------------------------
__device__ __noinline__ float exact_dist(const float* __restrict__ xp,
                                         const float* __restrict__ W,
                                         int q, float xs, const float* sm_wsq)
{
    const float* wp = W + (size_t)q * E;
    float acc = 0.0f;
    #pragma unroll 8
    for (int k = 0; k < E; k++) acc = fmaf(__ldg(xp + k), __ldg(wp + k), acc);
    float t = fmaf(-2.0f, acc, xs);
    return t + sm_wsq[q];
}

// ---------------------------------------------------------------------------
// Main kernel: tf32 mma.sync GEMM + margin-argmin + exact refine.
// 256 threads = 8 warps (warp grid 2x4: wm in {0,1} -> 64 rows, wn in 0..3 ->
// 32 cols). Warp tile 64x32, per-thread 4x4 m16n8 accum tiles.
// Smem tile layout (per 32-k chunk): elem (r, k) at float index
//   ((k>>2)*128 + (r ^ (k>>2)))*4 + (k&3)   -- conflict-free for both the 16B
// async stores and all fragment lds.32.
// ---------------------------------------------------------------------------
__global__ void __launch_bounds__(256, 1) vq_mma_kernel(const float* __restrict__ X,
                                                        const float* __restrict__ W)
{
    extern __shared__ char smem[];
    const uint32_t sb = smem_u32(smem);
    const int tid  = threadIdx.x;
    const int wid  = tid >> 5;
    const int lane = tid & 31;
    const int wm   = wid & 1;
    const int wn   = wid >> 1;
    const int g    = lane >> 2;
    const int l    = lane & 3;
    const int rb   = blockIdx.x;

    float* sm_wsq  = reinterpret_cast<float*>(smem + SOFF_WSQ);
    float* sm_best = reinterpret_cast<float*>(smem + SOFF_BEST);
    int*   sm_cnt  = reinterpret_cast<int*>(smem + SOFF_CNT);
    uint32_t cand_base = sb + SOFF_CAND + (uint32_t)tid * (CAND_CAP * 8);

    for (int i = tid; i < QROW; i += 256) sm_wsq[i] = g_wsq[i];

    // Per-thread row metadata: rowlocal rl = mtile*2 + p, row = wm*64 + mtile*16 + p*8 + g
    const float wsqmax = __int_as_float((int)g_wsqmax_bits);
    float xs_r[8], marg[8], runmin[8];
    #pragma unroll
    for (int rl = 0; rl < 8; rl++) {
        int row = wm * 64 + (rl >> 1) * 16 + (rl & 1) * 8 + g;
        float xs = g_xsq[rb * BM + row];
        xs_r[rl] = xs;
        marg[rl] = 0.0078125f * sqrtf(xs * wsqmax) + 2.5e-4f;  // 2x rigorous tf32 bound + slack
        runmin[rl] = __int_as_float(0x7f800000);
    }
    int cnt = 0;

    float acc[4][4][4];
    #pragma unroll
    for (int i = 0; i < 4; i++)
        #pragma unroll
        for (int j = 0; j < 4; j++)
            #pragma unroll
            for (int c = 0; c < 4; c++) acc[i][j][c] = 0.0f;

    __syncthreads();  // sm_wsq ready (stages don't overlap it)

    // ---- async copy of one 32-k chunk pair into stage buffer ----
    auto issue_stage = [&](int it) {
        int qt = it >> 4, kc = it & 15;
        uint32_t base = sb + SOFF_STAGE + (uint32_t)(it % STAGES) * STAGE_BYTES;
        const float* xg = X + (size_t)rb * BM * E + (size_t)kc * BK;
        const float* wg = W + (size_t)qt * BN * E + (size_t)kc * BK;
        #pragma unroll
        for (int i = 0; i < 4; i++) {
            int u = tid + i * 256;          // 0..1023
            int r = u >> 3, quad = u & 7;   // 8 consecutive tids = 128B contiguous gmem
            uint32_t off = (uint32_t)(quad * 128 + (r ^ quad)) * 16u;
            cp16(base + off,            xg + (size_t)r * E + quad * 4);
            cp16(base + A_BYTES + off,  wg + (size_t)r * E + quad * 4);
        }
        asm volatile("cp.async.commit_group;" ::: "memory");
    };

    issue_stage(0);
    issue_stage(1);

    for (int it = 0; it < NIT; it++) {
        const int qt = it >> 4, kc = it & 15;
        asm volatile("cp.async.wait_group 1;" ::: "memory");
        __syncthreads();
        if (it + 2 < NIT) issue_stage(it + 2);

        const uint32_t* As = reinterpret_cast<const uint32_t*>(
            smem + SOFF_STAGE + (size_t)(it % STAGES) * STAGE_BYTES);
        const uint32_t* Bs = As + BM * BK / 1 * 0 + A_BYTES / 4;

        #pragma unroll
        for (int k8 = 0; k8 < 4; k8++) {
            const int q0 = 2 * k8, q1 = 2 * k8 + 1;
            uint32_t a[4][4], b[4][2];
            #pragma unroll
            for (int i = 0; i < 4; i++) {
                int row = wm * 64 + i * 16 + g;
                int i0 = (q0 * 128 + (row ^ q0)) * 4 + l;
                int i1 = (q1 * 128 + (row ^ q1)) * 4 + l;
                a[i][0] = As[i0]; a[i][1] = As[i0 + 32];  // (row+8)^q == (row^q)+8
                a[i][2] = As[i1]; a[i][3] = As[i1 + 32];
            }
            #pragma unroll
            for (int j = 0; j < 4; j++) {
                int col = wn * 32 + j * 8 + g;
                b[j][0] = Bs[(q0 * 128 + (col ^ q0)) * 4 + l];
                b[j][1] = Bs[(q1 * 128 + (col ^ q1)) * 4 + l];
            }
            #pragma unroll
            for (int i = 0; i < 4; i++)
                #pragma unroll
                for (int j = 0; j < 4; j++)
                    mma_tf32(acc[i][j], a[i], b[j]);
        }

        if (kc == NKC - 1) {
            // epilogue for tile qt: dist, margin-capture, reset accum
            #pragma unroll
            for (int i = 0; i < 4; i++) {
                #pragma unroll
                for (int j = 0; j < 4; j++) {
                    int qb = qt * BN + wn * 32 + j * 8 + 2 * l;
                    #pragma unroll
                    for (int c = 0; c < 4; c++) {
                        const int rl = i * 2 + (c >> 1);
                        const int q  = qb + (c & 1);
                        float d = fmaf(-2.0f, acc[i][j][c], xs_r[rl]) + sm_wsq[q];
                        if (d <= runmin[rl] + marg[rl]) {
                            if (cnt < CAND_CAP) {
                                uint32_t ad = cand_base + (uint32_t)cnt * 8u;
                                int tag = (rl << 13) | q;
                                asm volatile("st.shared.v2.b32 [%0], {%1, %2};"
                                             :: "r"(ad), "r"(tag), "f"(d) : "memory");
                            }
                            cnt++;
                            if (d < runmin[rl]) runmin[rl] = d;
                        }
                        acc[i][j][c] = 0.0f;
                    }
                }
            }
        }
    }

    // publish per-thread results
    #pragma unroll
    for (int rl = 0; rl < 8; rl++) {
        int row = wm * 64 + (rl >> 1) * 16 + (rl & 1) * 8 + g;
        sm_best[row * 16 + wn * 4 + l] = runmin[rl];
    }
    sm_cnt[tid] = cnt;
    __syncthreads();

    // ---- exact refine: one thread per row ----
    if (tid < BM) {
        const int r = tid;
        const int grow = rb * BM + r;
        float rowmin = sm_best[r * 16 + 0];
        #pragma unroll
        for (int s = 1; s < 16; s++) rowmin = fminf(rowmin, sm_best[r * 16 + s]);
        const float xs = g_xsq[grow];
        const float mg = 0.0078125f * sqrtf(xs * wsqmax) + 2.5e-4f;
        const float thresh = rowmin + mg;

        // owner threads of row r: wid = wm + 2*wn, lane = g*4 + l
        const int o_wm = (r >> 6) & 1;
        const int o_g  = r & 7;
        const int o_rl = ((r >> 4) & 3) * 2 + ((r >> 3) & 1);
        const float* xp = X + (size_t)grow * E;

        bool overflow = false;
        float bd = __int_as_float(0x7f800000);
        int   bq = QROW;
        for (int onn = 0; onn < 4; onn++) {
            for (int ol = 0; ol < 4; ol++) {
                int otid = (o_wm + 2 * onn) * 32 + o_g * 4 + ol;
                int oc = sm_cnt[otid];
                if (oc > CAND_CAP) { overflow = true; oc = CAND_CAP; }
                const float* ce = reinterpret_cast<const float*>(
                    smem + SOFF_CAND + (size_t)otid * (CAND_CAP * 8));
                for (int e2 = 0; e2 < oc; e2++) {
                    int tag = __float_as_int(ce[e2 * 2]);
                    if ((tag >> 13) != o_rl) continue;
                    float dap = ce[e2 * 2 + 1];
                    if (dap > thresh) continue;
                    int q = tag & 8191;
                    float d = exact_dist(xp, W, q, xs, sm_wsq);
                    if (d < bd || (d == bd && q < bq)) { bd = d; bq = q; }
                }
            }
        }
        if (overflow) {  // safety net (statistically unreachable)
            for (int q = 0; q < QROW; q++) {
                float d = exact_dist(xp, W, q, xs, sm_wsq);
                if (d < bd || (d == bd && q < bq)) { bd = d; bq = q; }
            }
        }
        g_idx[grow] = bq;
    }
}

// ---------------------------------------------------------------------------
__global__ void __launch_bounds__(128) gather_kernel(const float* __restrict__ W,
                                                     float* __restrict__ outData,
                                                     float* __restrict__ outIdxF,
                                                     int writeIdx)
{
    int n = blockIdx.x;
    int q = g_idx[n];
    float4 v = reinterpret_cast<const float4*>(W + (size_t)q * E)[threadIdx.x];
    reinterpret_cast<float4*>(outData + (size_t)n * E)[threadIdx.x] = v;
    if (writeIdx && threadIdx.x == 0) outIdxF[n] = (float)q;
}

// ---------------------------------------------------------------------------
extern "C" void kernel_launch(void* const* d_in, const int* in_sizes, int n_in,
                              void* d_out, int out_size)
{
    const float* X = (const float*)d_in[0];
    const float* W = (const float*)d_in[1];
    int N = in_sizes[0] / E;
    int Q = in_sizes[1] / E;
    if (N != NROW || Q != QROW) return;

    float* out = (float*)d_out;

    static int attr_done = 0;
    if (!attr_done) {
        cudaFuncSetAttribute(vq_mma_kernel, cudaFuncAttributeMaxDynamicSharedMemorySize,
                             SMEM_TOTAL);
        attr_done = 1;
    }

    rowsq_x_kernel<<<(NROW + 7) / 8, 256>>>(X);
    rowsq_w_kernel<<<(QROW + 7) / 8, 256>>>(W);
    vq_mma_kernel<<<NROW / BM, 256, SMEM_TOTAL>>>(X, W);

    int writeIdx = (out_size >= NROW * E + NROW) ? 1 : 0;
    gather_kernel<<<NROW, 128>>>(W, out, out + (size_t)NROW * E, writeIdx);
}

// round 5
// speedup vs baseline: 60.0432x; 60.0432x over previous
#include <cuda_runtime.h>
#include <cuda_fp16.h>
#include <cstdint>
#include <math.h>

// ============================================================================
// Quantizing_12060268167756 — VQ lookup via warp-level tf32 mma.sync + exact
// refine. Capture: per-(thread,row) evict-worst top-8 rings (no fallback).
//   x: (16384, 512) f32   weight: (8192, 512) f32
//   out: q_data (N,E) f32, then q_idx (N,) as f32
// ============================================================================

#define E    512
#define NROW 16384
#define QROW 8192

#define BM   128
#define BN   128
#define BK   32
#define NQT  (QROW / BN)   // 64
#define NKC  (E / BK)      // 16
#define NIT  (NQT * NKC)   // 1024
#define STAGES 3
#define SLOTS  8           // evict-worst ring depth per (thread,row)

#define A_BYTES (BM * BK * 4)            // 16384
#define STAGE_BYTES (2 * A_BYTES)        // 32768

// dynamic smem offsets (bytes)
#define SOFF_STAGE 0
#define SOFF_WSQ   (STAGES * STAGE_BYTES)              // 98304, 32KB
#define SOFF_CAND  (SOFF_WSQ + QROW * 4)               // 131072, 64KB (256*8*8*4)
#define SOFF_BEST  (SOFF_CAND + 256 * 8 * SLOTS * 4)   // 196608, 8KB
#define SMEM_TOTAL (SOFF_BEST + BM * 16 * 4)           // 204800

__device__ float g_xsq[NROW];
__device__ float g_wsq[QROW];
__device__ int   g_idx[NROW];
__device__ unsigned int g_wsqmax_bits;

// ---------------------------------------------------------------------------
__device__ __forceinline__ uint32_t smem_u32(const void* p) {
    uint32_t a;
    asm("{ .reg .u64 t; cvta.to.shared.u64 t, %1; cvt.u32.u64 %0, t; }" : "=r"(a) : "l"(p));
    return a;
}
__device__ __forceinline__ void cp16(uint32_t dst, const void* src) {
    asm volatile("cp.async.cg.shared.global [%0], [%1], 16;"
                 :: "r"(dst), "l"(src) : "memory");
}
__device__ __forceinline__ void mma_tf32(float c[4], const uint32_t a[4], const uint32_t b[2]) {
    asm volatile(
        "mma.sync.aligned.m16n8k8.row.col.f32.tf32.tf32.f32 "
        "{%0,%1,%2,%3}, {%4,%5,%6,%7}, {%8,%9}, {%0,%1,%2,%3};"
        : "+f"(c[0]), "+f"(c[1]), "+f"(c[2]), "+f"(c[3])
        : "r"(a[0]), "r"(a[1]), "r"(a[2]), "r"(a[3]), "r"(b[0]), "r"(b[1]));
}

// Evict-worst insert into an 8-slot ring. Entry = (q<<16) | f16bits(d-xs+2),
// value field strictly positive -> unsigned-bit compare is value-monotone.
__device__ __forceinline__ void cand_insert(uint32_t* ring, int q, float drel) {
    uint32_t nb = (uint32_t)__half_as_ushort(__float2half_rn(drel));
    int wi = 0; uint32_t wb = ring[0] & 0xFFFFu;
    #pragma unroll
    for (int s = 1; s < SLOTS; s++) {
        uint32_t b = ring[s] & 0xFFFFu;
        if (b > wb) { wb = b; wi = s; }
    }
    if (nb < wb) ring[wi] = ((uint32_t)q << 16) | nb;
}

// ---------------------------------------------------------------------------
// Row sum-of-squares (fp64 accumulate -> correctly-rounded f32).
// ---------------------------------------------------------------------------
__global__ void __launch_bounds__(256) rowsq_x_kernel(const float* __restrict__ X)
{
    if (blockIdx.x == 0 && threadIdx.x == 0) g_wsqmax_bits = 0u;
    int row = blockIdx.x * 8 + (threadIdx.x >> 5);
    if (row >= NROW) return;
    int lane = threadIdx.x & 31;
    const float* p = X + (size_t)row * E;
    double s = 0.0;
    #pragma unroll
    for (int c = lane; c < E; c += 32) { float v = p[c]; s += (double)v * (double)v; }
    #pragma unroll
    for (int o = 16; o > 0; o >>= 1) s += __shfl_down_sync(0xffffffffu, s, o);
    if (lane == 0) g_xsq[row] = (float)s;
}

__global__ void __launch_bounds__(256) rowsq_w_kernel(const float* __restrict__ W)
{
    int row = blockIdx.x * 8 + (threadIdx.x >> 5);
    if (row >= QROW) return;
    int lane = threadIdx.x & 31;
    const float* p = W + (size_t)row * E;
    double s = 0.0;
    #pragma unroll
    for (int c = lane; c < E; c += 32) { float v = p[c]; s += (double)v * (double)v; }
    #pragma unroll
    for (int o = 16; o > 0; o >>= 1) s += __shfl_down_sync(0xffffffffu, s, o);
    if (lane == 0) {
        float f = (float)s;
        g_wsq[row] = f;
        atomicMax(&g_wsqmax_bits, (unsigned int)__float_as_int(f));  // f >= 0
    }
}

// ---------------------------------------------------------------------------
// Exact distance — bit-identical to R1's (which matched the reference):
// serial ascending-k fp32 FMA chain; t = fl(xs - 2*acc); d = t + wsq.
// ---------------------------------------------------------------------------
__device__ __noinline__ float exact_dist(const float* __restrict__ xp,
                                         const float* __restrict__ W,
                                         int q, float xs, const float* sm_wsq)
{
    const float* wp = W + (size_t)q * E;
    float acc = 0.0f;
    #pragma unroll 8
    for (int k = 0; k < E; k++) acc = fmaf(__ldg(xp + k), __ldg(wp + k), acc);
    float t = fmaf(-2.0f, acc, xs);
    return t + sm_wsq[q];
}

// ---------------------------------------------------------------------------
// Main kernel: tf32 mma.sync GEMM + margin-argmin + exact refine.
// 256 threads = 8 warps (2x4 warp grid), warp tile 64x32, 4x4 m16n8 accums.
// Smem tile layout per 32-k chunk: (r,k) at float idx
//   ((k>>2)*128 + (r ^ (k>>2)))*4 + (k&3)  — conflict-free stores + lds.32.
// ---------------------------------------------------------------------------
__global__ void __launch_bounds__(256, 1) vq_mma_kernel(const float* __restrict__ X,
                                                        const float* __restrict__ W)
{
    extern __shared__ char smem[];
    const uint32_t sb = smem_u32(smem);
    const int tid  = threadIdx.x;
    const int wid  = tid >> 5;
    const int lane = tid & 31;
    const int wm   = wid & 1;
    const int wn   = wid >> 1;
    const int g    = lane >> 2;
    const int l    = lane & 3;
    const int rb   = blockIdx.x;

    float*    sm_wsq  = reinterpret_cast<float*>(smem + SOFF_WSQ);
    float*    sm_best = reinterpret_cast<float*>(smem + SOFF_BEST);
    uint32_t* sm_cand = reinterpret_cast<uint32_t*>(smem + SOFF_CAND);

    for (int i = tid; i < QROW; i += 256) sm_wsq[i] = g_wsq[i];
    // init candidate rings to (q=0, +inf)
    #pragma unroll
    for (int s = 0; s < 8 * SLOTS; s++) sm_cand[tid * 8 * SLOTS + s] = 0x00007C00u;

    const float wsqmax = __int_as_float((int)g_wsqmax_bits);
    float xs_r[8], marg[8], runmin[8];
    #pragma unroll
    for (int rl = 0; rl < 8; rl++) {
        int row = wm * 64 + (rl >> 1) * 16 + (rl & 1) * 8 + g;
        float xs = g_xsq[rb * BM + row];
        xs_r[rl] = xs;
        marg[rl] = 0.0078125f * sqrtf(xs * wsqmax) + 2.5e-4f;  // 2x rigorous tf32 bound
        runmin[rl] = __int_as_float(0x7f800000);
    }

    float acc[4][4][4];
    #pragma unroll
    for (int i = 0; i < 4; i++)
        #pragma unroll
        for (int j = 0; j < 4; j++)
            #pragma unroll
            for (int c = 0; c < 4; c++) acc[i][j][c] = 0.0f;

    __syncthreads();

    auto issue_stage = [&](int it) {
        int qt = it >> 4, kc = it & 15;
        uint32_t base = sb + SOFF_STAGE + (uint32_t)(it % STAGES) * STAGE_BYTES;
        const float* xg = X + (size_t)rb * BM * E + (size_t)kc * BK;
        const float* wg = W + (size_t)qt * BN * E + (size_t)kc * BK;
        #pragma unroll
        for (int i = 0; i < 4; i++) {
            int u = tid + i * 256;
            int r = u >> 3, quad = u & 7;
            uint32_t off = (uint32_t)(quad * 128 + (r ^ quad)) * 16u;
            cp16(base + off,           xg + (size_t)r * E + quad * 4);
            cp16(base + A_BYTES + off, wg + (size_t)r * E + quad * 4);
        }
        asm volatile("cp.async.commit_group;" ::: "memory");
    };

    issue_stage(0);
    issue_stage(1);

    for (int it = 0; it < NIT; it++) {
        const int qt = it >> 4, kc = it & 15;
        asm volatile("cp.async.wait_group 1;" ::: "memory");
        __syncthreads();
        if (it + 2 < NIT) issue_stage(it + 2);

        const uint32_t* As = reinterpret_cast<const uint32_t*>(
            smem + SOFF_STAGE + (size_t)(it % STAGES) * STAGE_BYTES);
        const uint32_t* Bs = As + A_BYTES / 4;

        #pragma unroll
        for (int k8 = 0; k8 < 4; k8++) {
            const int q0 = 2 * k8, q1 = 2 * k8 + 1;
            uint32_t a[4][4], b[4][2];
            #pragma unroll
            for (int i = 0; i < 4; i++) {
                int row = wm * 64 + i * 16 + g;
                int i0 = (q0 * 128 + (row ^ q0)) * 4 + l;
                int i1 = (q1 * 128 + (row ^ q1)) * 4 + l;
                a[i][0] = As[i0]; a[i][1] = As[i0 + 32];
                a[i][2] = As[i1]; a[i][3] = As[i1 + 32];
            }
            #pragma unroll
            for (int j = 0; j < 4; j++) {
                int col = wn * 32 + j * 8 + g;
                b[j][0] = Bs[(q0 * 128 + (col ^ q0)) * 4 + l];
                b[j][1] = Bs[(q1 * 128 + (col ^ q1)) * 4 + l];
            }
            #pragma unroll
            for (int i = 0; i < 4; i++)
                #pragma unroll
                for (int j = 0; j < 4; j++)
                    mma_tf32(acc[i][j], a[i], b[j]);
        }

        if (kc == NKC - 1) {
            #pragma unroll
            for (int i = 0; i < 4; i++) {
                #pragma unroll
                for (int j = 0; j < 4; j++) {
                    int qb = qt * BN + wn * 32 + j * 8 + 2 * l;
                    #pragma unroll
                    for (int c = 0; c < 4; c++) {
                        const int rl = i * 2 + (c >> 1);
                        const int q  = qb + (c & 1);
                        float d = fmaf(-2.0f, acc[i][j][c], xs_r[rl]) + sm_wsq[q];
                        if (d <= runmin[rl] + marg[rl]) {
                            cand_insert(&sm_cand[(tid * 8 + rl) * SLOTS], q,
                                        d - xs_r[rl] + 2.0f);
                            if (d < runmin[rl]) runmin[rl] = d;
                        }
                        acc[i][j][c] = 0.0f;
                    }
                }
            }
        }
    }

    #pragma unroll
    for (int rl = 0; rl < 8; rl++) {
        int row = wm * 64 + (rl >> 1) * 16 + (rl & 1) * 8 + g;
        sm_best[row * 16 + wn * 4 + l] = runmin[rl];
    }
    __syncthreads();

    // ---- exact refine: one thread per row ----
    if (tid < BM) {
        const int r = tid;
        const int grow = rb * BM + r;
        float rowmin = sm_best[r * 16 + 0];
        #pragma unroll
        for (int s = 1; s < 16; s++) rowmin = fminf(rowmin, sm_best[r * 16 + s]);
        const float xs = g_xsq[grow];
        const float mg = 0.0078125f * sqrtf(xs * wsqmax) + 2.5e-4f;
        // filter threshold in drel units (+3e-3 covers the f16 quantization)
        const float trel = (rowmin - xs + 2.0f) + mg + 3.0e-3f;

        const int o_wm = (r >> 6) & 1;
        const int o_g  = r & 7;
        const int o_rl = ((r >> 4) & 3) * 2 + ((r >> 3) & 1);
        const float* xp = X + (size_t)grow * E;

        float bd = __int_as_float(0x7f800000);
        int   bq = QROW;
        for (int onn = 0; onn < 4; onn++) {
            for (int ol = 0; ol < 4; ol++) {
                int otid = (o_wm + 2 * onn) * 32 + o_g * 4 + ol;
                const uint32_t* ring = &sm_cand[(otid * 8 + o_rl) * SLOTS];
                #pragma unroll
                for (int s = 0; s < SLOTS; s++) {
                    uint32_t e2 = ring[s];
                    float dr = __half2float(__ushort_as_half((unsigned short)(e2 & 0xFFFFu)));
                    if (dr > trel) continue;
                    int q = (int)(e2 >> 16);
                    float d = exact_dist(xp, W, q, xs, sm_wsq);
                    if (d < bd || (d == bd && q < bq)) { bd = d; bq = q; }
                }
            }
        }
        g_idx[grow] = bq;
    }
}

// ---------------------------------------------------------------------------
__global__ void __launch_bounds__(128) gather_kernel(const float* __restrict__ W,
                                                     float* __restrict__ outData,
                                                     float* __restrict__ outIdxF,
                                                     int writeIdx)
{
    int n = blockIdx.x;
    int q = g_idx[n];
    float4 v = reinterpret_cast<const float4*>(W + (size_t)q * E)[threadIdx.x];
    reinterpret_cast<float4*>(outData + (size_t)n * E)[threadIdx.x] = v;
    if (writeIdx && threadIdx.x == 0) outIdxF[n] = (float)q;
}

// ---------------------------------------------------------------------------
extern "C" void kernel_launch(void* const* d_in, const int* in_sizes, int n_in,
                              void* d_out, int out_size)
{
    const float* X = (const float*)d_in[0];
    const float* W = (const float*)d_in[1];
    int N = in_sizes[0] / E;
    int Q = in_sizes[1] / E;
    if (N != NROW || Q != QROW) return;

    float* out = (float*)d_out;

    static int attr_done = 0;
    if (!attr_done) {
        cudaFuncSetAttribute(vq_mma_kernel, cudaFuncAttributeMaxDynamicSharedMemorySize,
                             SMEM_TOTAL);
        attr_done = 1;
    }

    rowsq_x_kernel<<<(NROW + 7) / 8, 256>>>(X);
    rowsq_w_kernel<<<(QROW + 7) / 8, 256>>>(W);
    vq_mma_kernel<<<NROW / BM, 256, SMEM_TOTAL>>>(X, W);

    int writeIdx = (out_size >= NROW * E + NROW) ? 1 : 0;
    gather_kernel<<<NROW, 128>>>(W, out, out + (size_t)NROW * E, writeIdx);
}